// round 15
// baseline (speedup 1.0000x reference)
#include <cuda.h>
#include <cuda_runtime.h>

// GraphNorm, persistent TMA-both-ways pipeline (R13 structure, 512 threads).
//   out = a*x + b,  a = gnw*rsqrt(var+eps), b = gnb - a*m*msc
//   var = E[x^2] - 2*(m*msc)*m + (m*msc)^2  (single sweep)
//
// Tile = (graph, 16-col chunk) = 512x16 fp32 = 32 KB. Ring of 3 SMEM buffers.
// One elected thread issues 2-box TMA loads (mbarrier complete_tx) and, after
// in-place apply, 2-box TMA stores (bulk_group, drained asynchronously).
// 512 thr/CTA (16 warps), 2 CTAs/SM, 304 persistent CTAs — double the warps
// of R13 to cover the per-tile latency chains.

#define TILE_D    16
#define THREADS   512
#define ROW_TILE  512
#define BOX_ROWS  256
#define NWARPS    (THREADS / 32)          // 16
#define NBUF      3
#define BUF_ELEMS (ROW_TILE * TILE_D)     // 8192 floats = 32 KB
#define PS_ELEMS  (NWARPS * TILE_D)       // 256 floats
#define TPR       4                       // threads per row (float4)
#define ROWSTEP   (THREADS / TPR)         // 128 rows per pass
#define NPASS     (ROW_TILE / ROWSTEP)    // 4
#define TILE_BYTES (BUF_ELEMS * 4)
#define EPSV      1e-6f
#define NCTA      304                     // 2 per SM x 152 SMs

#define SMEM_BYTES (NBUF*TILE_BYTES + 2*PS_ELEMS*4 + 64)

__device__ __forceinline__ unsigned smem_u32(const void* p) {
    return (unsigned)__cvta_generic_to_shared(p);
}
__device__ __forceinline__ void mbar_init(unsigned mbar, unsigned count) {
    asm volatile("mbarrier.init.shared.b64 [%0], %1;" :: "r"(mbar), "r"(count) : "memory");
}
__device__ __forceinline__ void mbar_expect_tx(unsigned mbar, unsigned bytes) {
    asm volatile("mbarrier.arrive.expect_tx.shared.b64 _, [%0], %1;"
                 :: "r"(mbar), "r"(bytes) : "memory");
}
__device__ __forceinline__ void mbar_wait(unsigned mbar, unsigned parity) {
    asm volatile(
        "{\n\t.reg .pred P;\n"
        "W_%=:\n\t"
        "mbarrier.try_wait.parity.acquire.cta.shared::cta.b64 P, [%0], %1, 0x989680;\n\t"
        "@P bra D_%=;\n\t"
        "bra W_%=;\n"
        "D_%=:\n\t}"
        :: "r"(mbar), "r"(parity) : "memory");
}
__device__ __forceinline__ void tma_load_2d(unsigned sdst, const CUtensorMap* tm,
                                            int cx, int cy, unsigned mbar) {
    asm volatile(
        "cp.async.bulk.tensor.2d.shared::cta.global.tile.mbarrier::complete_tx::bytes "
        "[%0], [%1, {%2, %3}], [%4];"
        :: "r"(sdst), "l"(tm), "r"(cx), "r"(cy), "r"(mbar) : "memory");
}
__device__ __forceinline__ void tma_store_2d(const CUtensorMap* tm,
                                             int cx, int cy, unsigned ssrc) {
    asm volatile(
        "cp.async.bulk.tensor.2d.global.shared::cta.tile.bulk_group "
        "[%0, {%1, %2}], [%3];"
        :: "l"(tm), "r"(cx), "r"(cy), "r"(ssrc) : "memory");
}
__device__ __forceinline__ void tma_commit() {
    asm volatile("cp.async.bulk.commit_group;" ::: "memory");
}
template <int N> __device__ __forceinline__ void tma_wait_group() {
    asm volatile("cp.async.bulk.wait_group %0;" :: "n"(N) : "memory");
}
__device__ __forceinline__ void fence_async() {
    asm volatile("fence.proxy.async.shared::cta;" ::: "memory");
}

__device__ __forceinline__ void acc4(float4 v, float4& s1, float4& s2) {
    s1.x += v.x; s1.y += v.y; s1.z += v.z; s1.w += v.w;
    s2.x = fmaf(v.x, v.x, s2.x);
    s2.y = fmaf(v.y, v.y, s2.y);
    s2.z = fmaf(v.z, v.z, s2.z);
    s2.w = fmaf(v.w, v.w, s2.w);
}

__global__ __launch_bounds__(THREADS, 2)
void graphnorm_tma_kernel(const __grid_constant__ CUtensorMap tmx,
                          const __grid_constant__ CUtensorMap tmo,
                          const float* __restrict__ x,
                          const float* __restrict__ gnw,
                          const float* __restrict__ gnb,
                          const float* __restrict__ msc,
                          const int* __restrict__ bn,
                          float* __restrict__ out,
                          int D, int B)
{
    extern __shared__ float smem[];
    float* ps1 = smem + NBUF * BUF_ELEMS;
    float* ps2 = ps1 + PS_ELEMS;
    unsigned long long* mb = (unsigned long long*)(ps2 + PS_ELEMS);

    const int tid  = threadIdx.x;
    const int wid  = tid >> 5;
    const int lane = tid & 31;
    const int ncc  = D / TILE_D;
    const int ntiles = B * ncc;

    const int l4   = (tid & (TPR - 1)) * 4;   // 0,4,8,12
    const int row0 = tid / TPR;               // 0..127

    const int t0 = blockIdx.x;
    const int stride = gridDim.x;
    if (t0 >= ntiles) return;

    if (tid == 0) {
        #pragma unroll
        for (int s = 0; s < NBUF; ++s) mbar_init(smem_u32(&mb[s]), 1);
    }
    __syncthreads();

    unsigned phases = 0;

    int pgP = 0; long long startP = 0; int tP = t0;
    int pg = 0;  long long pstart = 0; int t = t0;

    // prologue: issue load of tile t0 into slot 0
    {
        const int g = tP / ncc;
        while (pgP < g) startP += (long long)bn[pgP++];
        const int cx = (tP % ncc) * TILE_D;
        const int cy = (int)startP;
        if (tid == 0) {
            unsigned m = smem_u32(&mb[0]);
            mbar_expect_tx(m, 2 * BOX_ROWS * TILE_D * 4);
            tma_load_2d(smem_u32(smem), &tmx, cx, cy, m);
            tma_load_2d(smem_u32(smem + BOX_ROWS * TILE_D), &tmx, cx, cy + BOX_ROWS, m);
        }
        tP += stride;
    }

    int i = 0;
    for (;;) {
        const int slot_c = i % NBUF;
        const int slot_n = (i + 1) % NBUF;

        // issue next tile's load (slot_n's old store, tile i-2, drained via
        // wait_group<1> before reuse)
        const bool has_next = (tP < ntiles);
        if (has_next) {
            const int gn = tP / ncc;
            while (pgP < gn) startP += (long long)bn[pgP++];
            const int cx = (tP % ncc) * TILE_D;
            const int cy = (int)startP;
            if (tid == 0) {
                tma_wait_group<1>();
                unsigned m = smem_u32(&mb[slot_n]);
                mbar_expect_tx(m, 2 * BOX_ROWS * TILE_D * 4);
                float* nb = smem + slot_n * BUF_ELEMS;
                tma_load_2d(smem_u32(nb), &tmx, cx, cy, m);
                tma_load_2d(smem_u32(nb + BOX_ROWS * TILE_D), &tmx, cx, cy + BOX_ROWS, m);
            }
            tP += stride;
        }

        // current tile metadata
        const int g = t / ncc;
        while (pg < g) pstart += (long long)bn[pg++];
        const int cnt = bn[g];
        const int cpn = min(cnt, ROW_TILE);
        const int cc  = t % ncc;
        float* cb = smem + slot_c * BUF_ELEMS;
        const float* cxg = x + pstart * (long long)D + cc * TILE_D;

        mbar_wait(smem_u32(&mb[slot_c]), (phases >> slot_c) & 1u);
        phases ^= 1u << slot_c;

        // ---- reduce (capture in registers) ----
        float4 v[NPASS];
        float4 s1 = make_float4(0.f, 0.f, 0.f, 0.f);
        float4 s2 = make_float4(0.f, 0.f, 0.f, 0.f);
        const bool full = (cnt == ROW_TILE);
        if (full) {
            const float* tp = cb + row0 * TILE_D + l4;
            #pragma unroll
            for (int it = 0; it < NPASS; ++it) {
                v[it] = *(const float4*)(tp + it * ROWSTEP * TILE_D);
                acc4(v[it], s1, s2);
            }
        } else {
            for (int r = row0; r < cpn; r += ROWSTEP)
                acc4(*(const float4*)(cb + r * TILE_D + l4), s1, s2);
            for (int r = ROW_TILE + row0; r < cnt; r += ROWSTEP)
                acc4(*(const float4*)(cxg + (long long)r * D + l4), s1, s2);
        }

        #pragma unroll
        for (int off = TPR; off < 32; off <<= 1) {
            s1.x += __shfl_xor_sync(0xffffffffu, s1.x, off);
            s1.y += __shfl_xor_sync(0xffffffffu, s1.y, off);
            s1.z += __shfl_xor_sync(0xffffffffu, s1.z, off);
            s1.w += __shfl_xor_sync(0xffffffffu, s1.w, off);
            s2.x += __shfl_xor_sync(0xffffffffu, s2.x, off);
            s2.y += __shfl_xor_sync(0xffffffffu, s2.y, off);
            s2.z += __shfl_xor_sync(0xffffffffu, s2.z, off);
            s2.w += __shfl_xor_sync(0xffffffffu, s2.w, off);
        }
        if (lane < TPR) {
            *(float4*)(ps1 + wid * TILE_D + lane * 4) = s1;
            *(float4*)(ps2 + wid * TILE_D + lane * 4) = s2;
        }
        __syncthreads();

        // ---- warp-redundant coeffs, shfl broadcast ----
        float a = 0.f, b = 0.f;
        if (lane < TILE_D) {
            float t1 = 0.f, t2 = 0.f;
            #pragma unroll
            for (int k = 0; k < NWARPS; ++k) {
                t1 += ps1[k * TILE_D + lane];
                t2 += ps2[k * TILE_D + lane];
            }
            const float inv_n = 1.0f / (float)cnt;
            const float m    = t1 * inv_n;
            const float ex2  = t2 * inv_n;
            const float s    = msc[cc * TILE_D + lane];
            const float ms   = m * s;
            const float var  = ex2 - 2.f * ms * m + ms * ms;
            const float rstd = rsqrtf(var + EPSV);
            a = gnw[cc * TILE_D + lane] * rstd;
            b = gnb[cc * TILE_D + lane] - a * ms;
        }
        float4 av, bv;
        av.x = __shfl_sync(0xffffffffu, a, l4 + 0);
        av.y = __shfl_sync(0xffffffffu, a, l4 + 1);
        av.z = __shfl_sync(0xffffffffu, a, l4 + 2);
        av.w = __shfl_sync(0xffffffffu, a, l4 + 3);
        bv.x = __shfl_sync(0xffffffffu, b, l4 + 0);
        bv.y = __shfl_sync(0xffffffffu, b, l4 + 1);
        bv.z = __shfl_sync(0xffffffffu, b, l4 + 2);
        bv.w = __shfl_sync(0xffffffffu, b, l4 + 3);

        if (full) {
            // ---- apply in place (own slots; values held in regs) ----
            float* tp = cb + row0 * TILE_D + l4;
            #pragma unroll
            for (int it = 0; it < NPASS; ++it) {
                float4 o;
                o.x = fmaf(av.x, v[it].x, bv.x);
                o.y = fmaf(av.y, v[it].y, bv.y);
                o.z = fmaf(av.z, v[it].z, bv.z);
                o.w = fmaf(av.w, v[it].w, bv.w);
                *(float4*)(tp + it * ROWSTEP * TILE_D) = o;
            }
            __syncthreads();    // all STS done before TMA reads SMEM
            if (tid == 0) {
                fence_async();
                const int cx = cc * TILE_D;
                const int cy = (int)pstart;
                tma_store_2d(&tmo, cx, cy, smem_u32(cb));
                tma_store_2d(&tmo, cx, cy + BOX_ROWS, smem_u32(cb + BOX_ROWS * TILE_D));
                tma_commit();
            }
        } else {
            float* og = out + pstart * (long long)D + cc * TILE_D;
            for (int r = row0; r < cpn; r += ROWSTEP) {
                float4 w = *(const float4*)(cb + r * TILE_D + l4);
                float4 o;
                o.x = fmaf(av.x, w.x, bv.x);
                o.y = fmaf(av.y, w.y, bv.y);
                o.z = fmaf(av.z, w.z, bv.z);
                o.w = fmaf(av.w, w.w, bv.w);
                __stcs((float4*)(og + (long long)r * D + l4), o);
            }
            for (int r = ROW_TILE + row0; r < cnt; r += ROWSTEP) {
                float4 w = *(const float4*)(cxg + (long long)r * D + l4);
                float4 o;
                o.x = fmaf(av.x, w.x, bv.x);
                o.y = fmaf(av.y, w.y, bv.y);
                o.z = fmaf(av.z, w.z, bv.z);
                o.w = fmaf(av.w, w.w, bv.w);
                __stcs((float4*)(og + (long long)r * D + l4), o);
            }
            __syncthreads();
            if (tid == 0) tma_commit();   // empty group (positional accounting)
        }

        if (!has_next) break;
        t += stride;
        ++i;
    }
    if (tid == 0) tma_wait_group<0>();
}

// ---- host side: resolve cuTensorMapEncodeTiled through cudart ----
typedef CUresult (*PFN_encodeTiled)(
    CUtensorMap*, CUtensorMapDataType, cuuint32_t, void*,
    const cuuint64_t*, const cuuint64_t*, const cuuint32_t*, const cuuint32_t*,
    CUtensorMapInterleave, CUtensorMapSwizzle, CUtensorMapL2promotion,
    CUtensorMapFloatOOBfill);

static PFN_encodeTiled get_encode_fn()
{
    void* fn = nullptr;
    cudaDriverEntryPointQueryResult st;
#if CUDART_VERSION >= 12050
    cudaGetDriverEntryPointByVersion("cuTensorMapEncodeTiled", &fn, 12000,
                                     cudaEnableDefault, &st);
#else
    cudaGetDriverEntryPoint("cuTensorMapEncodeTiled", &fn,
                            cudaEnableDefault, &st);
#endif
    return (PFN_encodeTiled)fn;
}

extern "C" void kernel_launch(void* const* d_in, const int* in_sizes, int n_in,
                              void* d_out, int out_size)
{
    const float* x   = (const float*)d_in[0];
    const float* gnw = (const float*)d_in[1];
    const float* gnb = (const float*)d_in[2];
    const float* msc = (const float*)d_in[3];
    const int*   bn  = (const int*)d_in[4];
    float* out = (float*)d_out;

    const int D = in_sizes[1];                 // HIDDEN
    const int B = in_sizes[4];                 // NUM_GRAPHS
    const long long N = in_sizes[0] / D;       // total rows

    PFN_encodeTiled encode = get_encode_fn();

    CUtensorMap tmx, tmo;
    {
        cuuint64_t dims[2]    = {(cuuint64_t)D, (cuuint64_t)N};
        cuuint64_t strides[1] = {(cuuint64_t)D * sizeof(float)};
        cuuint32_t box[2]     = {TILE_D, BOX_ROWS};
        cuuint32_t es[2]      = {1, 1};
        encode(&tmx, CU_TENSOR_MAP_DATA_TYPE_FLOAT32, 2,
               (void*)x, dims, strides, box, es,
               CU_TENSOR_MAP_INTERLEAVE_NONE, CU_TENSOR_MAP_SWIZZLE_NONE,
               CU_TENSOR_MAP_L2_PROMOTION_L2_256B,
               CU_TENSOR_MAP_FLOAT_OOB_FILL_NONE);
        encode(&tmo, CU_TENSOR_MAP_DATA_TYPE_FLOAT32, 2,
               (void*)out, dims, strides, box, es,
               CU_TENSOR_MAP_INTERLEAVE_NONE, CU_TENSOR_MAP_SWIZZLE_NONE,
               CU_TENSOR_MAP_L2_PROMOTION_L2_128B,
               CU_TENSOR_MAP_FLOAT_OOB_FILL_NONE);
    }

    cudaFuncSetAttribute(graphnorm_tma_kernel,
                         cudaFuncAttributeMaxDynamicSharedMemorySize,
                         (int)SMEM_BYTES);

    int ntiles = B * (D / TILE_D);
    int grid = ntiles < NCTA ? ntiles : NCTA;
    graphnorm_tma_kernel<<<grid, THREADS, SMEM_BYTES>>>(tmx, tmo, x, gnw, gnb,
                                                        msc, bn, out, D, B);
}

// round 16
// speedup vs baseline: 1.2574x; 1.2574x over previous
#include <cuda_runtime.h>
#include <cuda_bf16.h>

// GraphNorm, persistent double-buffered cp.async pipeline (R10 structure)
// + L2 evict_first policy on BOTH streams (reads via cache_hint, writes via .cs).
//   out = a*x + b,  a = gnw*rsqrt(var+eps), b = gnb - a*m*msc
//   var = E[x^2] - 2*(m*msc)*m + (m*msc)^2  (single sweep)
//
// Tile = (graph, 16-col chunk): 512x16 fp32 = 32 KB (64B rows).
// 256 thr/CTA, 3 CTAs/SM, 456 persistent CTAs; tile t+1 prefetched after
// barrier (1) of tile t. Neither x nor out is ever re-read, so both streams
// are marked evict-first to keep L2 free for write buffering.

#define TILE_D    16
#define THREADS   256
#define ROW_TILE  512
#define NWARPS    (THREADS / 32)          // 8
#define BUF_ELEMS (ROW_TILE * TILE_D)     // 8192 floats = 32 KB
#define TPR       4                       // threads per row (float4)
#define ROWSTEP   (THREADS / TPR)         // 64 rows per pass
#define NPASS     (ROW_TILE / ROWSTEP)    // 8
#define EPSV      1e-6f
#define NCTA      456                     // 3 per SM x 152 SMs

#define SMEM_BYTES ((2*BUF_ELEMS + 2*NWARPS*TILE_D) * sizeof(float))

__device__ __forceinline__ unsigned smem_u32(const void* p) {
    return (unsigned)__cvta_generic_to_shared(p);
}
__device__ __forceinline__ unsigned long long mk_evict_first_policy() {
    unsigned long long pol;
    asm("createpolicy.fractional.L2::evict_first.b64 %0, 1.0;" : "=l"(pol));
    return pol;
}
__device__ __forceinline__ void cp16_ef(unsigned dst, const void* src,
                                        unsigned long long pol) {
    asm volatile("cp.async.cg.shared.global.L2::cache_hint [%0], [%1], 16, %2;"
                 :: "r"(dst), "l"(src), "l"(pol));
}
__device__ __forceinline__ void cp_commit() {
    asm volatile("cp.async.commit_group;");
}
template <int N> __device__ __forceinline__ void cp_wait() {
    asm volatile("cp.async.wait_group %0;" :: "n"(N));
}

__device__ __forceinline__ void acc4(float4 v, float4& s1, float4& s2) {
    s1.x += v.x; s1.y += v.y; s1.z += v.z; s1.w += v.w;
    s2.x = fmaf(v.x, v.x, s2.x);
    s2.y = fmaf(v.y, v.y, s2.y);
    s2.z = fmaf(v.z, v.z, s2.z);
    s2.w = fmaf(v.w, v.w, s2.w);
}

__global__ __launch_bounds__(THREADS, 3)
void graphnorm_kernel(const float* __restrict__ x,
                      const float* __restrict__ gnw,
                      const float* __restrict__ gnb,
                      const float* __restrict__ msc,
                      const int* __restrict__ bn,
                      float* __restrict__ out,
                      int D, int B)
{
    extern __shared__ float smem[];
    float* buf0 = smem;
    float* buf1 = smem + BUF_ELEMS;
    float* ps1  = smem + 2 * BUF_ELEMS;       // [NWARPS][TILE_D]
    float* ps2  = ps1 + NWARPS * TILE_D;

    const int tid  = threadIdx.x;
    const int wid  = tid >> 5;
    const int lane = tid & 31;
    const int ncc  = D / TILE_D;
    const int ntiles = B * ncc;

    const int l4   = (tid & (TPR - 1)) * 4;   // 0,4,8,12
    const int row0 = tid / TPR;               // 0..63

    int t = blockIdx.x;
    const int stride = gridDim.x;
    if (t >= ntiles) return;

    const unsigned long long pol = mk_evict_first_policy();

    int pg = 0;
    long long pstart = 0;

#define ISSUE_TILE(dstbuf, XG, CPN)                                           \
    do {                                                                      \
        const float* pp = (XG) + (long long)row0 * D + l4;                    \
        unsigned dd = smem_u32((dstbuf) + row0 * TILE_D + l4);                \
        if ((CPN) == ROW_TILE) {                                              \
            _Pragma("unroll")                                                 \
            for (int it = 0; it < NPASS; ++it) {                              \
                cp16_ef(dd, pp, pol);                                         \
                pp += (long long)ROWSTEP * D;                                 \
                dd += ROWSTEP * TILE_D * 4;                                   \
            }                                                                 \
        } else {                                                              \
            for (int r = row0; r < (CPN); r += ROWSTEP) {                     \
                cp16_ef(dd, pp, pol);                                         \
                pp += (long long)ROWSTEP * D;                                 \
                dd += ROWSTEP * TILE_D * 4;                                   \
            }                                                                 \
        }                                                                     \
        cp_commit();                                                          \
    } while (0)

    // ---- prologue: resolve + issue first tile into buf0 ----
    int g = t / ncc;
    while (pg < g) pstart += (long long)bn[pg++];
    int cnt = bn[g];
    int cpn = min(cnt, ROW_TILE);
    const float* xg = x + pstart * (long long)D + (t % ncc) * TILE_D;
    ISSUE_TILE(buf0, xg, cpn);

    int bsel = 0;
    for (;;) {
        const long long cstart = pstart;
        const int   ccnt = cnt, ccpn = cpn;
        const int   cc   = t % ncc;
        const float* cxg = xg;
        float* cb = bsel ? buf1 : buf0;

        // resolve next tile's metadata (off the critical path, before wait)
        const int tn = t + stride;
        const bool has_next = (tn < ntiles);
        if (has_next) {
            const int gn = tn / ncc;
            while (pg < gn) pstart += (long long)bn[pg++];
            cnt = bn[gn];
            cpn = min(cnt, ROW_TILE);
            xg = x + pstart * (long long)D + (tn % ncc) * TILE_D;
        }

        cp_wait<0>();        // current tile landed
        __syncthreads();     // (1) visible; other buffer free (apply of t-1 done)

        if (has_next)
            ISSUE_TILE(bsel ? buf0 : buf1, xg, cpn);

        // ---- reduce current tile ----
        float4 s1 = make_float4(0.f, 0.f, 0.f, 0.f);
        float4 s2 = make_float4(0.f, 0.f, 0.f, 0.f);
        if (ccpn == ROW_TILE) {
            const float* tp = cb + row0 * TILE_D + l4;
            #pragma unroll
            for (int it = 0; it < NPASS; it += 4) {
                float4 v0 = *(const float4*)(tp + (it + 0) * ROWSTEP * TILE_D);
                float4 v1 = *(const float4*)(tp + (it + 1) * ROWSTEP * TILE_D);
                float4 v2 = *(const float4*)(tp + (it + 2) * ROWSTEP * TILE_D);
                float4 v3 = *(const float4*)(tp + (it + 3) * ROWSTEP * TILE_D);
                acc4(v0, s1, s2); acc4(v1, s1, s2);
                acc4(v2, s1, s2); acc4(v3, s1, s2);
            }
        } else {
            for (int r = row0; r < ccpn; r += ROWSTEP)
                acc4(*(const float4*)(cb + r * TILE_D + l4), s1, s2);
        }
        for (int r = ROW_TILE + row0; r < ccnt; r += ROWSTEP)
            acc4(*(const float4*)(cxg + (long long)r * D + l4), s1, s2);

        #pragma unroll
        for (int off = TPR; off < 32; off <<= 1) {
            s1.x += __shfl_xor_sync(0xffffffffu, s1.x, off);
            s1.y += __shfl_xor_sync(0xffffffffu, s1.y, off);
            s1.z += __shfl_xor_sync(0xffffffffu, s1.z, off);
            s1.w += __shfl_xor_sync(0xffffffffu, s1.w, off);
            s2.x += __shfl_xor_sync(0xffffffffu, s2.x, off);
            s2.y += __shfl_xor_sync(0xffffffffu, s2.y, off);
            s2.z += __shfl_xor_sync(0xffffffffu, s2.z, off);
            s2.w += __shfl_xor_sync(0xffffffffu, s2.w, off);
        }
        if (lane < TPR) {
            *(float4*)(ps1 + wid * TILE_D + lane * 4) = s1;
            *(float4*)(ps2 + wid * TILE_D + lane * 4) = s2;
        }
        __syncthreads();     // (2) partials visible

        // ---- warp-redundant coeffs, shfl broadcast (no barrier) ----
        float a = 0.f, b = 0.f;
        if (lane < TILE_D) {
            float t1 = 0.f, t2 = 0.f;
            #pragma unroll
            for (int k = 0; k < NWARPS; ++k) {
                t1 += ps1[k * TILE_D + lane];
                t2 += ps2[k * TILE_D + lane];
            }
            const float inv_n = 1.0f / (float)ccnt;
            const float m    = t1 * inv_n;
            const float ex2  = t2 * inv_n;
            const float s    = msc[cc * TILE_D + lane];
            const float ms   = m * s;
            const float var  = ex2 - 2.f * ms * m + ms * ms;
            const float rstd = rsqrtf(var + EPSV);
            a = gnw[cc * TILE_D + lane] * rstd;
            b = gnb[cc * TILE_D + lane] - a * ms;
        }
        float4 av, bv;
        av.x = __shfl_sync(0xffffffffu, a, l4 + 0);
        av.y = __shfl_sync(0xffffffffu, a, l4 + 1);
        av.z = __shfl_sync(0xffffffffu, a, l4 + 2);
        av.w = __shfl_sync(0xffffffffu, a, l4 + 3);
        bv.x = __shfl_sync(0xffffffffu, b, l4 + 0);
        bv.y = __shfl_sync(0xffffffffu, b, l4 + 1);
        bv.z = __shfl_sync(0xffffffffu, b, l4 + 2);
        bv.w = __shfl_sync(0xffffffffu, b, l4 + 3);

        // ---- apply + streaming store (evict-first: out never re-read) ----
        float* og = out + cstart * (long long)D + cc * TILE_D;
        if (ccpn == ROW_TILE) {
            const float* tp = cb + row0 * TILE_D + l4;
            float* q = og + (long long)row0 * D + l4;
            const long long rstep = (long long)ROWSTEP * D;
            #pragma unroll
            for (int it = 0; it < NPASS; it += 4) {
                float4 v0 = *(const float4*)(tp + (it + 0) * ROWSTEP * TILE_D);
                float4 v1 = *(const float4*)(tp + (it + 1) * ROWSTEP * TILE_D);
                float4 v2 = *(const float4*)(tp + (it + 2) * ROWSTEP * TILE_D);
                float4 v3 = *(const float4*)(tp + (it + 3) * ROWSTEP * TILE_D);
                float4 o0, o1, o2, o3;
                o0.x = fmaf(av.x, v0.x, bv.x); o0.y = fmaf(av.y, v0.y, bv.y);
                o0.z = fmaf(av.z, v0.z, bv.z); o0.w = fmaf(av.w, v0.w, bv.w);
                o1.x = fmaf(av.x, v1.x, bv.x); o1.y = fmaf(av.y, v1.y, bv.y);
                o1.z = fmaf(av.z, v1.z, bv.z); o1.w = fmaf(av.w, v1.w, bv.w);
                o2.x = fmaf(av.x, v2.x, bv.x); o2.y = fmaf(av.y, v2.y, bv.y);
                o2.z = fmaf(av.z, v2.z, bv.z); o2.w = fmaf(av.w, v2.w, bv.w);
                o3.x = fmaf(av.x, v3.x, bv.x); o3.y = fmaf(av.y, v3.y, bv.y);
                o3.z = fmaf(av.z, v3.z, bv.z); o3.w = fmaf(av.w, v3.w, bv.w);
                __stcs((float4*)(q + (it + 0) * rstep), o0);
                __stcs((float4*)(q + (it + 1) * rstep), o1);
                __stcs((float4*)(q + (it + 2) * rstep), o2);
                __stcs((float4*)(q + (it + 3) * rstep), o3);
            }
        } else {
            for (int r = row0; r < ccpn; r += ROWSTEP) {
                float4 v = *(const float4*)(cb + r * TILE_D + l4);
                float4 o;
                o.x = fmaf(av.x, v.x, bv.x);
                o.y = fmaf(av.y, v.y, bv.y);
                o.z = fmaf(av.z, v.z, bv.z);
                o.w = fmaf(av.w, v.w, bv.w);
                __stcs((float4*)(og + (long long)r * D + l4), o);
            }
        }
        for (int r = ROW_TILE + row0; r < ccnt; r += ROWSTEP) {
            float4 v = *(const float4*)(cxg + (long long)r * D + l4);
            float4 o;
            o.x = fmaf(av.x, v.x, bv.x);
            o.y = fmaf(av.y, v.y, bv.y);
            o.z = fmaf(av.z, v.z, bv.z);
            o.w = fmaf(av.w, v.w, bv.w);
            __stcs((float4*)(og + (long long)r * D + l4), o);
        }

        if (!has_next) break;
        t = tn;
        bsel ^= 1;
    }
#undef ISSUE_TILE
}

extern "C" void kernel_launch(void* const* d_in, const int* in_sizes, int n_in,
                              void* d_out, int out_size)
{
    const float* x   = (const float*)d_in[0];
    const float* gnw = (const float*)d_in[1];
    const float* gnb = (const float*)d_in[2];
    const float* msc = (const float*)d_in[3];
    const int*   bn  = (const int*)d_in[4];
    float* out = (float*)d_out;

    const int D = in_sizes[1];     // HIDDEN
    const int B = in_sizes[4];     // NUM_GRAPHS

    cudaFuncSetAttribute(graphnorm_kernel,
                         cudaFuncAttributeMaxDynamicSharedMemorySize,
                         (int)SMEM_BYTES);

    int ntiles = B * (D / TILE_D);
    int grid = ntiles < NCTA ? ntiles : NCTA;
    graphnorm_kernel<<<grid, THREADS, SMEM_BYTES>>>(x, gnw, gnb, msc, bn, out, D, B);
}

// round 17
// speedup vs baseline: 1.2685x; 1.0088x over previous
#include <cuda_runtime.h>
#include <cuda_bf16.h>

// GraphNorm — FINAL (converged at the mixed-R/W HBM ceiling, ~4.9 TB/s).
// Persistent double-buffered cp.async pipeline with L2 evict_first on both
// streams (reads via cache_hint, writes via st.global.cs).
//   out = a*x + b,  a = gnw*rsqrt(var+eps), b = gnb - a*m*msc
//   var = E[x^2] - 2*(m*msc)*m + (m*msc)^2  (single sweep: sum x, sum x^2)
//
// Tile = (graph, 16-col chunk): 512x16 fp32 = 32 KB (64B rows).
// 256 thr/CTA, 3 CTAs/SM, 456 persistent CTAs; tile t+1 prefetched after
// barrier (1) of tile t. Neither x nor out is ever re-read, so both streams
// are marked evict-first to keep L2 free for write buffering.
//
// Session evidence (R2-R16): pacing (warp/cp.async/TMA), depth (1-3),
// occupancy (512-2048 thr/SM), granularity (32/64/128B), barriers (4->1),
// and L2 policy all leave DRAM duty pinned at 57-62% => hardware ceiling.

#define TILE_D    16
#define THREADS   256
#define ROW_TILE  512
#define NWARPS    (THREADS / 32)          // 8
#define BUF_ELEMS (ROW_TILE * TILE_D)     // 8192 floats = 32 KB
#define TPR       4                       // threads per row (float4)
#define ROWSTEP   (THREADS / TPR)         // 64 rows per pass
#define NPASS     (ROW_TILE / ROWSTEP)    // 8
#define EPSV      1e-6f
#define NCTA      456                     // 3 per SM x 152 SMs

#define SMEM_BYTES ((2*BUF_ELEMS + 2*NWARPS*TILE_D) * sizeof(float))

__device__ __forceinline__ unsigned smem_u32(const void* p) {
    return (unsigned)__cvta_generic_to_shared(p);
}
__device__ __forceinline__ unsigned long long mk_evict_first_policy() {
    unsigned long long pol;
    asm("createpolicy.fractional.L2::evict_first.b64 %0, 1.0;" : "=l"(pol));
    return pol;
}
__device__ __forceinline__ void cp16_ef(unsigned dst, const void* src,
                                        unsigned long long pol) {
    asm volatile("cp.async.cg.shared.global.L2::cache_hint [%0], [%1], 16, %2;"
                 :: "r"(dst), "l"(src), "l"(pol));
}
__device__ __forceinline__ void cp_commit() {
    asm volatile("cp.async.commit_group;");
}
template <int N> __device__ __forceinline__ void cp_wait() {
    asm volatile("cp.async.wait_group %0;" :: "n"(N));
}

__device__ __forceinline__ void acc4(float4 v, float4& s1, float4& s2) {
    s1.x += v.x; s1.y += v.y; s1.z += v.z; s1.w += v.w;
    s2.x = fmaf(v.x, v.x, s2.x);
    s2.y = fmaf(v.y, v.y, s2.y);
    s2.z = fmaf(v.z, v.z, s2.z);
    s2.w = fmaf(v.w, v.w, s2.w);
}

__global__ __launch_bounds__(THREADS, 3)
void graphnorm_kernel(const float* __restrict__ x,
                      const float* __restrict__ gnw,
                      const float* __restrict__ gnb,
                      const float* __restrict__ msc,
                      const int* __restrict__ bn,
                      float* __restrict__ out,
                      int D, int B)
{
    extern __shared__ float smem[];
    float* buf0 = smem;
    float* buf1 = smem + BUF_ELEMS;
    float* ps1  = smem + 2 * BUF_ELEMS;       // [NWARPS][TILE_D]
    float* ps2  = ps1 + NWARPS * TILE_D;

    const int tid  = threadIdx.x;
    const int wid  = tid >> 5;
    const int lane = tid & 31;
    const int ncc  = D / TILE_D;
    const int ntiles = B * ncc;

    const int l4   = (tid & (TPR - 1)) * 4;   // 0,4,8,12
    const int row0 = tid / TPR;               // 0..63

    int t = blockIdx.x;
    const int stride = gridDim.x;
    if (t >= ntiles) return;

    const unsigned long long pol = mk_evict_first_policy();

    int pg = 0;
    long long pstart = 0;

#define ISSUE_TILE(dstbuf, XG, CPN)                                           \
    do {                                                                      \
        const float* pp = (XG) + (long long)row0 * D + l4;                    \
        unsigned dd = smem_u32((dstbuf) + row0 * TILE_D + l4);                \
        if ((CPN) == ROW_TILE) {                                              \
            _Pragma("unroll")                                                 \
            for (int it = 0; it < NPASS; ++it) {                              \
                cp16_ef(dd, pp, pol);                                         \
                pp += (long long)ROWSTEP * D;                                 \
                dd += ROWSTEP * TILE_D * 4;                                   \
            }                                                                 \
        } else {                                                              \
            for (int r = row0; r < (CPN); r += ROWSTEP) {                     \
                cp16_ef(dd, pp, pol);                                         \
                pp += (long long)ROWSTEP * D;                                 \
                dd += ROWSTEP * TILE_D * 4;                                   \
            }                                                                 \
        }                                                                     \
        cp_commit();                                                          \
    } while (0)

    // ---- prologue: resolve + issue first tile into buf0 ----
    int g = t / ncc;
    while (pg < g) pstart += (long long)bn[pg++];
    int cnt = bn[g];
    int cpn = min(cnt, ROW_TILE);
    const float* xg = x + pstart * (long long)D + (t % ncc) * TILE_D;
    ISSUE_TILE(buf0, xg, cpn);

    int bsel = 0;
    for (;;) {
        const long long cstart = pstart;
        const int   ccnt = cnt, ccpn = cpn;
        const int   cc   = t % ncc;
        const float* cxg = xg;
        float* cb = bsel ? buf1 : buf0;

        // resolve next tile's metadata (off the critical path, before wait)
        const int tn = t + stride;
        const bool has_next = (tn < ntiles);
        if (has_next) {
            const int gn = tn / ncc;
            while (pg < gn) pstart += (long long)bn[pg++];
            cnt = bn[gn];
            cpn = min(cnt, ROW_TILE);
            xg = x + pstart * (long long)D + (tn % ncc) * TILE_D;
        }

        cp_wait<0>();        // current tile landed
        __syncthreads();     // (1) visible; other buffer free (apply of t-1 done)

        if (has_next)
            ISSUE_TILE(bsel ? buf0 : buf1, xg, cpn);

        // ---- reduce current tile ----
        float4 s1 = make_float4(0.f, 0.f, 0.f, 0.f);
        float4 s2 = make_float4(0.f, 0.f, 0.f, 0.f);
        if (ccpn == ROW_TILE) {
            const float* tp = cb + row0 * TILE_D + l4;
            #pragma unroll
            for (int it = 0; it < NPASS; it += 4) {
                float4 v0 = *(const float4*)(tp + (it + 0) * ROWSTEP * TILE_D);
                float4 v1 = *(const float4*)(tp + (it + 1) * ROWSTEP * TILE_D);
                float4 v2 = *(const float4*)(tp + (it + 2) * ROWSTEP * TILE_D);
                float4 v3 = *(const float4*)(tp + (it + 3) * ROWSTEP * TILE_D);
                acc4(v0, s1, s2); acc4(v1, s1, s2);
                acc4(v2, s1, s2); acc4(v3, s1, s2);
            }
        } else {
            for (int r = row0; r < ccpn; r += ROWSTEP)
                acc4(*(const float4*)(cb + r * TILE_D + l4), s1, s2);
        }
        for (int r = ROW_TILE + row0; r < ccnt; r += ROWSTEP)
            acc4(*(const float4*)(cxg + (long long)r * D + l4), s1, s2);

        #pragma unroll
        for (int off = TPR; off < 32; off <<= 1) {
            s1.x += __shfl_xor_sync(0xffffffffu, s1.x, off);
            s1.y += __shfl_xor_sync(0xffffffffu, s1.y, off);
            s1.z += __shfl_xor_sync(0xffffffffu, s1.z, off);
            s1.w += __shfl_xor_sync(0xffffffffu, s1.w, off);
            s2.x += __shfl_xor_sync(0xffffffffu, s2.x, off);
            s2.y += __shfl_xor_sync(0xffffffffu, s2.y, off);
            s2.z += __shfl_xor_sync(0xffffffffu, s2.z, off);
            s2.w += __shfl_xor_sync(0xffffffffu, s2.w, off);
        }
        if (lane < TPR) {
            *(float4*)(ps1 + wid * TILE_D + lane * 4) = s1;
            *(float4*)(ps2 + wid * TILE_D + lane * 4) = s2;
        }
        __syncthreads();     // (2) partials visible

        // ---- warp-redundant coeffs, shfl broadcast (no barrier) ----
        float a = 0.f, b = 0.f;
        if (lane < TILE_D) {
            float t1 = 0.f, t2 = 0.f;
            #pragma unroll
            for (int k = 0; k < NWARPS; ++k) {
                t1 += ps1[k * TILE_D + lane];
                t2 += ps2[k * TILE_D + lane];
            }
            const float inv_n = 1.0f / (float)ccnt;
            const float m    = t1 * inv_n;
            const float ex2  = t2 * inv_n;
            const float s    = msc[cc * TILE_D + lane];
            const float ms   = m * s;
            const float var  = ex2 - 2.f * ms * m + ms * ms;
            const float rstd = rsqrtf(var + EPSV);
            a = gnw[cc * TILE_D + lane] * rstd;
            b = gnb[cc * TILE_D + lane] - a * ms;
        }
        float4 av, bv;
        av.x = __shfl_sync(0xffffffffu, a, l4 + 0);
        av.y = __shfl_sync(0xffffffffu, a, l4 + 1);
        av.z = __shfl_sync(0xffffffffu, a, l4 + 2);
        av.w = __shfl_sync(0xffffffffu, a, l4 + 3);
        bv.x = __shfl_sync(0xffffffffu, b, l4 + 0);
        bv.y = __shfl_sync(0xffffffffu, b, l4 + 1);
        bv.z = __shfl_sync(0xffffffffu, b, l4 + 2);
        bv.w = __shfl_sync(0xffffffffu, b, l4 + 3);

        // ---- apply + streaming store (evict-first: out never re-read) ----
        float* og = out + cstart * (long long)D + cc * TILE_D;
        if (ccpn == ROW_TILE) {
            const float* tp = cb + row0 * TILE_D + l4;
            float* q = og + (long long)row0 * D + l4;
            const long long rstep = (long long)ROWSTEP * D;
            #pragma unroll
            for (int it = 0; it < NPASS; it += 4) {
                float4 v0 = *(const float4*)(tp + (it + 0) * ROWSTEP * TILE_D);
                float4 v1 = *(const float4*)(tp + (it + 1) * ROWSTEP * TILE_D);
                float4 v2 = *(const float4*)(tp + (it + 2) * ROWSTEP * TILE_D);
                float4 v3 = *(const float4*)(tp + (it + 3) * ROWSTEP * TILE_D);
                float4 o0, o1, o2, o3;
                o0.x = fmaf(av.x, v0.x, bv.x); o0.y = fmaf(av.y, v0.y, bv.y);
                o0.z = fmaf(av.z, v0.z, bv.z); o0.w = fmaf(av.w, v0.w, bv.w);
                o1.x = fmaf(av.x, v1.x, bv.x); o1.y = fmaf(av.y, v1.y, bv.y);
                o1.z = fmaf(av.z, v1.z, bv.z); o1.w = fmaf(av.w, v1.w, bv.w);
                o2.x = fmaf(av.x, v2.x, bv.x); o2.y = fmaf(av.y, v2.y, bv.y);
                o2.z = fmaf(av.z, v2.z, bv.z); o2.w = fmaf(av.w, v2.w, bv.w);
                o3.x = fmaf(av.x, v3.x, bv.x); o3.y = fmaf(av.y, v3.y, bv.y);
                o3.z = fmaf(av.z, v3.z, bv.z); o3.w = fmaf(av.w, v3.w, bv.w);
                __stcs((float4*)(q + (it + 0) * rstep), o0);
                __stcs((float4*)(q + (it + 1) * rstep), o1);
                __stcs((float4*)(q + (it + 2) * rstep), o2);
                __stcs((float4*)(q + (it + 3) * rstep), o3);
            }
        } else {
            for (int r = row0; r < ccpn; r += ROWSTEP) {
                float4 v = *(const float4*)(cb + r * TILE_D + l4);
                float4 o;
                o.x = fmaf(av.x, v.x, bv.x);
                o.y = fmaf(av.y, v.y, bv.y);
                o.z = fmaf(av.z, v.z, bv.z);
                o.w = fmaf(av.w, v.w, bv.w);
                __stcs((float4*)(og + (long long)r * D + l4), o);
            }
        }
        for (int r = ROW_TILE + row0; r < ccnt; r += ROWSTEP) {
            float4 v = *(const float4*)(cxg + (long long)r * D + l4);
            float4 o;
            o.x = fmaf(av.x, v.x, bv.x);
            o.y = fmaf(av.y, v.y, bv.y);
            o.z = fmaf(av.z, v.z, bv.z);
            o.w = fmaf(av.w, v.w, bv.w);
            __stcs((float4*)(og + (long long)r * D + l4), o);
        }

        if (!has_next) break;
        t = tn;
        bsel ^= 1;
    }
#undef ISSUE_TILE
}

extern "C" void kernel_launch(void* const* d_in, const int* in_sizes, int n_in,
                              void* d_out, int out_size)
{
    const float* x   = (const float*)d_in[0];
    const float* gnw = (const float*)d_in[1];
    const float* gnb = (const float*)d_in[2];
    const float* msc = (const float*)d_in[3];
    const int*   bn  = (const int*)d_in[4];
    float* out = (float*)d_out;

    const int D = in_sizes[1];     // HIDDEN
    const int B = in_sizes[4];     // NUM_GRAPHS

    cudaFuncSetAttribute(graphnorm_kernel,
                         cudaFuncAttributeMaxDynamicSharedMemorySize,
                         (int)SMEM_BYTES);

    int ntiles = B * (D / TILE_D);
    int grid = ntiles < NCTA ? ntiles : NCTA;
    graphnorm_kernel<<<grid, THREADS, SMEM_BYTES>>>(x, gnw, gnb, msc, bn, out, D, B);
}